// round 14
// baseline (speedup 1.0000x reference)
#include <cuda_runtime.h>
#include <math.h>
#include <stdint.h>

#define T_LEN 2048
#define B_SZ  2
#define EMB   768
#define NH    12
#define HD    64
#define MROWS 4096
#define L2E   1.4426950408889634f
#define MAXS_L2E (24.0f * L2E)

// ---------------- scratch (device globals) ---------------------------------
__device__ float g_q[MROWS * EMB];
__device__ float g_k[MROWS * EMB];
__device__ float g_v[MROWS * EMB];
__device__ float g_att[MROWS * EMB];
__device__ float g_bias[NH * 4096];   // [h][rel+2048], pre-scaled by log2(e)

// ---------------- helpers ---------------------------------------------------
__device__ __forceinline__ uint32_t smu32(const void* p) {
    uint32_t a;
    asm("{.reg .u64 t; cvta.to.shared.u64 t, %1; cvt.u32.u64 %0, t;}"
        : "=r"(a) : "l"(p));
    return a;
}
__device__ __forceinline__ void cp16(uint32_t d, const void* s) {
    asm volatile("cp.async.cg.shared.global [%0], [%1], 16;" :: "r"(d), "l"(s));
}
__device__ __forceinline__ void cp_commit() { asm volatile("cp.async.commit_group;"); }
template <int N> __device__ __forceinline__ void cp_wait() {
    asm volatile("cp.async.wait_group %0;" :: "n"(N));
}
__device__ __forceinline__ uint32_t tfu(float x) {
    uint32_t r;
    asm("cvt.rna.tf32.f32 %0, %1;" : "=r"(r) : "f"(x));
    return r;
}
__device__ __forceinline__ float tff(float x) { return __uint_as_float(tfu(x)); }
__device__ __forceinline__ float ex2(float x) {
    float r;
    asm("ex2.approx.f32 %0, %1;" : "=f"(r) : "f"(x));
    return r;
}
__device__ __forceinline__ void mma_tf32(float c[4], const uint32_t a[4],
                                         const uint32_t b[2]) {
    asm volatile(
        "mma.sync.aligned.m16n8k8.row.col.f32.tf32.tf32.f32 "
        "{%0,%1,%2,%3},{%4,%5,%6,%7},{%8,%9},{%0,%1,%2,%3};"
        : "+f"(c[0]), "+f"(c[1]), "+f"(c[2]), "+f"(c[3])
        : "r"(a[0]), "r"(a[1]), "r"(a[2]), "r"(a[3]), "r"(b[0]), "r"(b[1]));
}

// ---------------- T5 relative bias LUT (pre-scaled by log2 e) --------------
__global__ void bias_lut_kernel(const float* __restrict__ rel_bias) {
    int idx = blockIdx.x * blockDim.x + threadIdx.x;
    if (idx >= NH * 4096) return;
    int h   = idx >> 12;
    int rel = (idx & 4095) - 2048;
    int bucket = (rel > 0) ? 16 : 0;
    int rp = rel < 0 ? -rel : rel;
    if (rp < 8) {
        bucket += rp;
    } else {
        float lf = logf((float)rp / 8.0f) / 2.7725887298583984f * 8.0f;
        int large = 8 + (int)lf;
        bucket += (large < 15) ? large : 15;
    }
    g_bias[idx] = rel_bias[bucket * NH + h] * L2E;
}

// ------- tf32 SGEMM v2: 4 warps x (m64,n32), vectorized staging ------------
#define ASTR 36    // ≡4 mod 32
#define BSTR 72    // ≡8 mod 32
template <bool CVT>
__global__ __launch_bounds__(128, 4)
void sgemm_tf32_kernel(const float* __restrict__ X, const float* __restrict__ W,
                       const float* __restrict__ bias, float* __restrict__ Y,
                       float scale) {
    __shared__ float As[128 * ASTR];
    __shared__ float Bs[32 * BSTR];

    int tid = threadIdx.x, lane = tid & 31, w = tid >> 5;  // w in [0,4)
    int wm = w & 1, wn = w >> 1;                            // 2x2 warp grid
    int lr = lane >> 2, lc = lane & 3;
    int m0 = blockIdx.y << 7, n0 = blockIdx.x << 6;

    float acc[4][4][4];
#pragma unroll
    for (int mt = 0; mt < 4; mt++)
#pragma unroll
        for (int nt = 0; nt < 4; nt++)
#pragma unroll
            for (int i = 0; i < 4; i++) acc[mt][nt][i] = 0.f;

    for (int k0 = 0; k0 < EMB; k0 += 32) {
        __syncthreads();
        // X tile 128x32 -> As[m][k] (tf32, one STS.128 per float4)
#pragma unroll
        for (int i = 0; i < 8; i++) {
            int e = tid + i * 128;
            int row = e >> 3, kc = (e & 7) << 2;
            float4 v = *(const float4*)&X[(m0 + row) * EMB + k0 + kc];
            v.x = tff(v.x); v.y = tff(v.y); v.z = tff(v.z); v.w = tff(v.w);
            *(float4*)&As[row * ASTR + kc] = v;
        }
        // W tile 32x64 -> Bs[k][n]
#pragma unroll
        for (int i = 0; i < 4; i++) {
            int e = tid + i * 128;
            int k = e >> 4, nc = (e & 15) << 2;
            float4 v = *(const float4*)&W[(k0 + k) * EMB + n0 + nc];
            v.x = tff(v.x); v.y = tff(v.y); v.z = tff(v.z); v.w = tff(v.w);
            *(float4*)&Bs[k * BSTR + nc] = v;
        }
        __syncthreads();

#pragma unroll
        for (int ks = 0; ks < 4; ks++) {
            int kk = ks * 8;
            uint32_t a[4][4], bf[4][2];
#pragma unroll
            for (int mt = 0; mt < 4; mt++) {
                int base = wm * 64 + mt * 16;
                a[mt][0] = __float_as_uint(As[(base + lr)     * ASTR + kk + lc]);
                a[mt][1] = __float_as_uint(As[(base + lr + 8) * ASTR + kk + lc]);
                a[mt][2] = __float_as_uint(As[(base + lr)     * ASTR + kk + lc + 4]);
                a[mt][3] = __float_as_uint(As[(base + lr + 8) * ASTR + kk + lc + 4]);
            }
#pragma unroll
            for (int nt = 0; nt < 4; nt++) {
                int nb = wn * 32 + nt * 8 + lr;
                bf[nt][0] = __float_as_uint(Bs[(kk + lc)     * BSTR + nb]);
                bf[nt][1] = __float_as_uint(Bs[(kk + lc + 4) * BSTR + nb]);
            }
#pragma unroll
            for (int mt = 0; mt < 4; mt++)
#pragma unroll
                for (int nt = 0; nt < 4; nt++)
                    mma_tf32(acc[mt][nt], a[mt], bf[nt]);
        }
    }

#pragma unroll
    for (int mt = 0; mt < 4; mt++) {
        int row = m0 + wm * 64 + mt * 16 + lr;
#pragma unroll
        for (int nt = 0; nt < 4; nt++) {
            int col = n0 + wn * 32 + nt * 8 + 2 * lc;
            float b0 = bias[col], b1 = bias[col + 1];
            float o00 = (acc[mt][nt][0] + b0) * scale;
            float o01 = (acc[mt][nt][1] + b1) * scale;
            float o10 = (acc[mt][nt][2] + b0) * scale;
            float o11 = (acc[mt][nt][3] + b1) * scale;
            if (CVT) { o00 = tff(o00); o01 = tff(o01); o10 = tff(o10); o11 = tff(o11); }
            *(float2*)&Y[row * EMB + col]       = make_float2(o00, o01);
            *(float2*)&Y[(row + 8) * EMB + col] = make_float2(o10, o11);
        }
    }
}

// -------- tf32 flash attention v5: 4 warps x m32, K/V frag reuse x2 --------
#define KST 68
#define VST 72
#define PST 36
#define SMK 0
#define KSTG 2176            // 32*68
#define SMV 6528             // 3*KSTG
#define VSTG 2304            // 32*72
#define SMP 13440            // SMV + 3*VSTG
#define SMB 18048            // SMP + 128*36
#define SMM 20224            // SMB + 2175, padded to 16B
#define SMTOT 20736          // floats -> 82944 B

__global__ __launch_bounds__(128, 2)
void attn_tf32_v5(const unsigned char* __restrict__ maskg) {
    extern __shared__ float sm[];
    int tid = threadIdx.x, lane = tid & 31, w = tid >> 5;   // w in [0,4)
    int lr = lane >> 2, lc = lane & 3;
    int bh = blockIdx.y;
    int b = bh / NH, h = bh % NH;
    int t0 = blockIdx.x * 128;
    uint32_t sbase = smu32(sm);
    unsigned char* smask = (unsigned char*)(sm + SMM);
    int r0l = w * 32 + lr;                 // warp covers rows [w*32, w*32+32)

    auto issue_kv = [&](int kt2, int slot) {
        int s0 = kt2 * 32;
#pragma unroll
        for (int i = 0; i < 4; i++) {
            int e = tid + i * 128;          // 512 float4 slots
            int row = e >> 4, c4 = (e & 15) << 2;
            cp16(sbase + (SMK + slot * KSTG + row * KST + c4) * 4,
                 &g_k[((s0 + row) * B_SZ + b) * EMB + h * HD + c4]);
        }
#pragma unroll
        for (int i = 0; i < 4; i++) {
            int e = tid + i * 128;
            int row = e >> 4, c4 = (e & 15) << 2;
            cp16(sbase + (SMV + slot * VSTG + row * VST + c4) * 4,
                 &g_v[((s0 + row) * B_SZ + b) * EMB + h * HD + c4]);
        }
    };

    // Q fragments for 2 m-tiles (loop-invariant; producer wrote tf32 bits)
    uint32_t qf[2][8][4];
#pragma unroll
    for (int mt = 0; mt < 2; mt++) {
        const float* q0 = &g_q[((t0 + r0l + mt * 16)     * B_SZ + b) * EMB + h * HD];
        const float* q1 = &g_q[((t0 + r0l + mt * 16 + 8) * B_SZ + b) * EMB + h * HD];
#pragma unroll
        for (int ks = 0; ks < 8; ks++) {
            int kk = ks * 8;
            qf[mt][ks][0] = __float_as_uint(q0[kk + lc]);
            qf[mt][ks][1] = __float_as_uint(q1[kk + lc]);
            qf[mt][ks][2] = __float_as_uint(q0[kk + lc + 4]);
            qf[mt][ks][3] = __float_as_uint(q1[kk + lc + 4]);
        }
    }

    // bias slice (fold -M*log2e), mask row
    for (int i = tid; i < 2175; i += 128)
        sm[SMB + i] = g_bias[h * 4096 + i + 1921 - t0] - MAXS_L2E;
    ((float4*)smask)[tid] = ((const float4*)(maskg + b * T_LEN))[tid];

    issue_kv(0, 0); cp_commit();
    issue_kv(1, 1); cp_commit();

    float o[2][8][4];
#pragma unroll
    for (int mt = 0; mt < 2; mt++)
#pragma unroll
        for (int nt = 0; nt < 8; nt++)
#pragma unroll
            for (int i = 0; i < 4; i++) o[mt][nt][i] = 0.f;
    float ls[2][2] = {{0.f, 0.f}, {0.f, 0.f}};

    for (int kt = 0; kt < 64; kt++) {
        cp_wait<1>();
        __syncthreads();
        if (kt + 2 < 64) issue_kv(kt + 2, (kt + 2) % 3);
        cp_commit();

        int slot = kt % 3;
        const float* Ks = sm + SMK + slot * KSTG;
        const float* Vs = sm + SMV + slot * VSTG;
        int s0 = kt * 32;

        // S = Q K^T  (m32 x n32 x k64); K-frags reused across both m-tiles
        float s4[2][4][4];
#pragma unroll
        for (int mt = 0; mt < 2; mt++)
#pragma unroll
            for (int nt = 0; nt < 4; nt++)
#pragma unroll
                for (int i = 0; i < 4; i++) s4[mt][nt][i] = 0.f;
#pragma unroll
        for (int ks = 0; ks < 8; ks++) {
            int kk = ks * 8;
            uint32_t bf[4][2];
#pragma unroll
            for (int nt = 0; nt < 4; nt++) {
                int nb = nt * 8 + lr;
                bf[nt][0] = __float_as_uint(Ks[nb * KST + kk + lc]);
                bf[nt][1] = __float_as_uint(Ks[nb * KST + kk + lc + 4]);
            }
#pragma unroll
            for (int mt = 0; mt < 2; mt++)
#pragma unroll
                for (int nt = 0; nt < 4; nt++)
                    mma_tf32(s4[mt][nt], qf[mt][ks], bf[nt]);
        }

        // p = 2^( s*log2e + (bias - M)*log2e + mask )
#pragma unroll
        for (int mt = 0; mt < 2; mt++) {
            int ra = r0l + mt * 16, rb = ra + 8;
#pragma unroll
            for (int nt = 0; nt < 4; nt++) {
                int c0 = nt * 8 + 2 * lc, c1 = c0 + 1;
                float mk0 = smask[s0 + c0] ? -1e30f : 0.f;
                float mk1 = smask[s0 + c1] ? -1e30f : 0.f;
                float pb00 = sm[SMB + s0 + c0 - ra + 127] + mk0;
                float pb01 = sm[SMB + s0 + c1 - ra + 127] + mk1;
                float pb10 = sm[SMB + s0 + c0 - rb + 127] + mk0;
                float pb11 = sm[SMB + s0 + c1 - rb + 127] + mk1;
                s4[mt][nt][0] = ex2(fmaf(s4[mt][nt][0], L2E, pb00));
                s4[mt][nt][1] = ex2(fmaf(s4[mt][nt][1], L2E, pb01));
                s4[mt][nt][2] = ex2(fmaf(s4[mt][nt][2], L2E, pb10));
                s4[mt][nt][3] = ex2(fmaf(s4[mt][nt][3], L2E, pb11));
                ls[mt][0] += s4[mt][nt][0] + s4[mt][nt][1];
                ls[mt][1] += s4[mt][nt][2] + s4[mt][nt][3];
            }
        }

        // stage P (tf32, warp-private 32 rows)
#pragma unroll
        for (int mt = 0; mt < 2; mt++) {
            int ra = r0l + mt * 16, rb = ra + 8;
#pragma unroll
            for (int nt = 0; nt < 4; nt++) {
                int c0 = nt * 8 + 2 * lc;
                *(float2*)&sm[SMP + ra * PST + c0] =
                    make_float2(tff(s4[mt][nt][0]), tff(s4[mt][nt][1]));
                *(float2*)&sm[SMP + rb * PST + c0] =
                    make_float2(tff(s4[mt][nt][2]), tff(s4[mt][nt][3]));
            }
        }
        __syncwarp();

        // O += P V  (m32 x n64 x k32); V-frags reused across both m-tiles
#pragma unroll
        for (int ks = 0; ks < 4; ks++) {
            int kk = ks * 8;
            uint32_t a[2][4], bf[8][2];
#pragma unroll
            for (int mt = 0; mt < 2; mt++) {
                int ra = r0l + mt * 16;
                a[mt][0] = __float_as_uint(sm[SMP + ra * PST + kk + lc]);
                a[mt][1] = __float_as_uint(sm[SMP + (ra + 8) * PST + kk + lc]);
                a[mt][2] = __float_as_uint(sm[SMP + ra * PST + kk + lc + 4]);
                a[mt][3] = __float_as_uint(sm[SMP + (ra + 8) * PST + kk + lc + 4]);
            }
#pragma unroll
            for (int nt = 0; nt < 8; nt++) {
                int nb = nt * 8 + lr;
                bf[nt][0] = __float_as_uint(Vs[(kk + lc)     * VST + nb]);
                bf[nt][1] = __float_as_uint(Vs[(kk + lc + 4) * VST + nb]);
            }
#pragma unroll
            for (int mt = 0; mt < 2; mt++)
#pragma unroll
                for (int nt = 0; nt < 8; nt++)
                    mma_tf32(o[mt][nt], a[mt], bf[nt]);
        }
    }

    // deferred row-sum reduce (quads share rows)
#pragma unroll
    for (int mt = 0; mt < 2; mt++) {
#pragma unroll
        for (int i = 0; i < 2; i++) {
            ls[mt][i] += __shfl_xor_sync(0xffffffffu, ls[mt][i], 1);
            ls[mt][i] += __shfl_xor_sync(0xffffffffu, ls[mt][i], 2);
        }
    }

#pragma unroll
    for (int mt = 0; mt < 2; mt++) {
        float inv0 = 1.0f / ls[mt][0], inv1 = 1.0f / ls[mt][1];
        int tra = t0 + r0l + mt * 16;
#pragma unroll
        for (int nt = 0; nt < 8; nt++) {
            int d = h * HD + nt * 8 + 2 * lc;
            *(float2*)&g_att[(tra * B_SZ + b) * EMB + d] =
                make_float2(o[mt][nt][0] * inv0, o[mt][nt][1] * inv0);
            *(float2*)&g_att[((tra + 8) * B_SZ + b) * EMB + d] =
                make_float2(o[mt][nt][2] * inv1, o[mt][nt][3] * inv1);
        }
    }
}

// ---------------- launch ---------------------------------------------------
extern "C" void kernel_launch(void* const* d_in, const int* in_sizes, int n_in,
                              void* d_out, int out_size) {
    const float* query = (const float*)d_in[0];
    const float* key   = (const float*)d_in[1];
    const float* value = (const float*)d_in[2];
    const unsigned char* mask = (const unsigned char*)d_in[3];
    const float* Wq = (const float*)d_in[4];
    const float* bq = (const float*)d_in[5];
    const float* Wk = (const float*)d_in[6];
    const float* bk = (const float*)d_in[7];
    const float* Wv = (const float*)d_in[8];
    const float* bv = (const float*)d_in[9];
    const float* Wo = (const float*)d_in[10];
    const float* bo = (const float*)d_in[11];
    const float* rel_bias = (const float*)d_in[12];
    float* out = (float*)d_out;

    float *pq, *pk, *pv, *patt;
    cudaGetSymbolAddress((void**)&pq,   g_q);
    cudaGetSymbolAddress((void**)&pk,   g_k);
    cudaGetSymbolAddress((void**)&pv,   g_v);
    cudaGetSymbolAddress((void**)&patt, g_att);

    const int ATTN_SMEM = SMTOT * 4;   // 82944
    cudaFuncSetAttribute(attn_tf32_v5,
                         cudaFuncAttributeMaxDynamicSharedMemorySize, ATTN_SMEM);

    bias_lut_kernel<<<(NH * 4096 + 255) / 256, 256>>>(rel_bias);

    dim3 gg(EMB / 64, MROWS / 128);   // (12, 32) = 384 CTAs
    sgemm_tf32_kernel<true><<<gg, 128>>>(query, Wq, bq, pq, 0.125f);
    sgemm_tf32_kernel<true><<<gg, 128>>>(key,   Wk, bk, pk, 1.0f);
    sgemm_tf32_kernel<true><<<gg, 128>>>(value, Wv, bv, pv, 1.0f);

    dim3 ga(T_LEN / 128, B_SZ * NH);  // (16, 24)
    attn_tf32_v5<<<ga, 128, ATTN_SMEM>>>(mask);

    sgemm_tf32_kernel<false><<<gg, 128>>>(patt, Wo, bo, out, 1.0f);
}

// round 15
// speedup vs baseline: 1.0600x; 1.0600x over previous
#include <cuda_runtime.h>
#include <math.h>
#include <stdint.h>

#define T_LEN 2048
#define B_SZ  2
#define EMB   768
#define NH    12
#define HD    64
#define MROWS 4096
#define L2E   1.4426950408889634f
#define MAXS_L2E (24.0f * L2E)

// ---------------- scratch (device globals) ---------------------------------
__device__ float g_q[MROWS * EMB];
__device__ float g_k[MROWS * EMB];
__device__ float g_v[MROWS * EMB];
__device__ float g_att[MROWS * EMB];
__device__ float g_bias[NH * 4096];   // [h][rel+2048], pre-scaled by log2(e)

// ---------------- helpers ---------------------------------------------------
__device__ __forceinline__ uint32_t smu32(const void* p) {
    uint32_t a;
    asm("{.reg .u64 t; cvta.to.shared.u64 t, %1; cvt.u32.u64 %0, t;}"
        : "=r"(a) : "l"(p));
    return a;
}
__device__ __forceinline__ void cp16(uint32_t d, const void* s) {
    asm volatile("cp.async.cg.shared.global [%0], [%1], 16;" :: "r"(d), "l"(s));
}
__device__ __forceinline__ void cp_commit() { asm volatile("cp.async.commit_group;"); }
template <int N> __device__ __forceinline__ void cp_wait() {
    asm volatile("cp.async.wait_group %0;" :: "n"(N));
}
__device__ __forceinline__ uint32_t tfu(float x) {
    uint32_t r;
    asm("cvt.rna.tf32.f32 %0, %1;" : "=r"(r) : "f"(x));
    return r;
}
__device__ __forceinline__ float tff(float x) { return __uint_as_float(tfu(x)); }
__device__ __forceinline__ float ex2(float x) {
    float r;
    asm("ex2.approx.f32 %0, %1;" : "=f"(r) : "f"(x));
    return r;
}
__device__ __forceinline__ void mma_tf32(float c[4], const uint32_t a[4],
                                         const uint32_t b[2]) {
    asm volatile(
        "mma.sync.aligned.m16n8k8.row.col.f32.tf32.tf32.f32 "
        "{%0,%1,%2,%3},{%4,%5,%6,%7},{%8,%9},{%0,%1,%2,%3};"
        : "+f"(c[0]), "+f"(c[1]), "+f"(c[2]), "+f"(c[3])
        : "r"(a[0]), "r"(a[1]), "r"(a[2]), "r"(a[3]), "r"(b[0]), "r"(b[1]));
}

// ---------------- T5 relative bias LUT (pre-scaled by log2 e) --------------
__global__ void bias_lut_kernel(const float* __restrict__ rel_bias) {
    int idx = blockIdx.x * blockDim.x + threadIdx.x;
    if (idx >= NH * 4096) return;
    int h   = idx >> 12;
    int rel = (idx & 4095) - 2048;
    int bucket = (rel > 0) ? 16 : 0;
    int rp = rel < 0 ? -rel : rel;
    if (rp < 8) {
        bucket += rp;
    } else {
        float lf = logf((float)rp / 8.0f) / 2.7725887298583984f * 8.0f;
        int large = 8 + (int)lf;
        bucket += (large < 15) ? large : 15;
    }
    g_bias[idx] = rel_bias[bucket * NH + h] * L2E;
}

// ---- tf32 SGEMM (round-13 engine + vectorized STS.128 staging) ------------
#define ASTR 36    // ≡4 mod 32
#define BSTR 72    // ≡8 mod 32
template <bool CVT>
__global__ __launch_bounds__(256, 3)
void sgemm_tf32_kernel(const float* __restrict__ X, const float* __restrict__ W,
                       const float* __restrict__ bias, float* __restrict__ Y,
                       float scale) {
    __shared__ float As[128 * ASTR];
    __shared__ float Bs[32 * BSTR];

    int tid = threadIdx.x, lane = tid & 31, w = tid >> 5;
    int wm = w & 3, wn = w >> 2, lr = lane >> 2, lc = lane & 3;
    int m0 = blockIdx.y << 7, n0 = blockIdx.x << 6;

    float acc[2][4][4];
#pragma unroll
    for (int mt = 0; mt < 2; mt++)
#pragma unroll
        for (int nt = 0; nt < 4; nt++)
#pragma unroll
            for (int i = 0; i < 4; i++) acc[mt][nt][i] = 0.f;

    for (int k0 = 0; k0 < EMB; k0 += 32) {
        __syncthreads();
        // X tile 128x32 -> As[m][k]: cvt in regs, one STS.128
#pragma unroll
        for (int i = 0; i < 4; i++) {
            int e = tid + i * 256;
            int row = e >> 3, kc = (e & 7) << 2;
            float4 v = *(const float4*)&X[(m0 + row) * EMB + k0 + kc];
            v.x = tff(v.x); v.y = tff(v.y); v.z = tff(v.z); v.w = tff(v.w);
            *(float4*)&As[row * ASTR + kc] = v;
        }
        // W tile 32x64 -> Bs[k][n]
#pragma unroll
        for (int i = 0; i < 2; i++) {
            int e = tid + i * 256;
            int k = e >> 4, nc = (e & 15) << 2;
            float4 v = *(const float4*)&W[(k0 + k) * EMB + n0 + nc];
            v.x = tff(v.x); v.y = tff(v.y); v.z = tff(v.z); v.w = tff(v.w);
            *(float4*)&Bs[k * BSTR + nc] = v;
        }
        __syncthreads();

#pragma unroll
        for (int ks = 0; ks < 4; ks++) {
            int kk = ks * 8;
            uint32_t a[2][4], bf[4][2];
#pragma unroll
            for (int mt = 0; mt < 2; mt++) {
                int base = wm * 32 + mt * 16;
                a[mt][0] = __float_as_uint(As[(base + lr)     * ASTR + kk + lc]);
                a[mt][1] = __float_as_uint(As[(base + lr + 8) * ASTR + kk + lc]);
                a[mt][2] = __float_as_uint(As[(base + lr)     * ASTR + kk + lc + 4]);
                a[mt][3] = __float_as_uint(As[(base + lr + 8) * ASTR + kk + lc + 4]);
            }
#pragma unroll
            for (int nt = 0; nt < 4; nt++) {
                int nb = wn * 32 + nt * 8 + lr;
                bf[nt][0] = __float_as_uint(Bs[(kk + lc)     * BSTR + nb]);
                bf[nt][1] = __float_as_uint(Bs[(kk + lc + 4) * BSTR + nb]);
            }
#pragma unroll
            for (int mt = 0; mt < 2; mt++)
#pragma unroll
                for (int nt = 0; nt < 4; nt++)
                    mma_tf32(acc[mt][nt], a[mt], bf[nt]);
        }
    }

#pragma unroll
    for (int mt = 0; mt < 2; mt++) {
        int row = m0 + wm * 32 + mt * 16 + lr;
#pragma unroll
        for (int nt = 0; nt < 4; nt++) {
            int col = n0 + wn * 32 + nt * 8 + 2 * lc;
            float b0 = bias[col], b1 = bias[col + 1];
            float o00 = (acc[mt][nt][0] + b0) * scale;
            float o01 = (acc[mt][nt][1] + b1) * scale;
            float o10 = (acc[mt][nt][2] + b0) * scale;
            float o11 = (acc[mt][nt][3] + b1) * scale;
            if (CVT) { o00 = tff(o00); o01 = tff(o01); o10 = tff(o10); o11 = tff(o11); }
            *(float2*)&Y[row * EMB + col]       = make_float2(o00, o01);
            *(float2*)&Y[(row + 8) * EMB + col] = make_float2(o10, o11);
        }
    }
}

// -------- tf32 flash attention v5: 4 warps x m32, K/V frag reuse x2 --------
#define KST 68
#define VST 72
#define PST 36
#define SMK 0
#define KSTG 2176            // 32*68
#define SMV 6528             // 3*KSTG
#define VSTG 2304            // 32*72
#define SMP 13440            // SMV + 3*VSTG
#define SMB 18048            // SMP + 128*36
#define SMM 20224            // SMB + 2175, padded to 16B
#define SMTOT 20736          // floats -> 82944 B

__global__ __launch_bounds__(128, 2)
void attn_tf32_v5(const unsigned char* __restrict__ maskg) {
    extern __shared__ float sm[];
    int tid = threadIdx.x, lane = tid & 31, w = tid >> 5;   // w in [0,4)
    int lr = lane >> 2, lc = lane & 3;
    int bh = blockIdx.y;
    int b = bh / NH, h = bh % NH;
    int t0 = blockIdx.x * 128;
    uint32_t sbase = smu32(sm);
    unsigned char* smask = (unsigned char*)(sm + SMM);
    int r0l = w * 32 + lr;                 // warp covers rows [w*32, w*32+32)

    auto issue_kv = [&](int kt2, int slot) {
        int s0 = kt2 * 32;
#pragma unroll
        for (int i = 0; i < 4; i++) {
            int e = tid + i * 128;          // 512 float4 slots
            int row = e >> 4, c4 = (e & 15) << 2;
            cp16(sbase + (SMK + slot * KSTG + row * KST + c4) * 4,
                 &g_k[((s0 + row) * B_SZ + b) * EMB + h * HD + c4]);
        }
#pragma unroll
        for (int i = 0; i < 4; i++) {
            int e = tid + i * 128;
            int row = e >> 4, c4 = (e & 15) << 2;
            cp16(sbase + (SMV + slot * VSTG + row * VST + c4) * 4,
                 &g_v[((s0 + row) * B_SZ + b) * EMB + h * HD + c4]);
        }
    };

    // Q fragments for 2 m-tiles (loop-invariant; producer wrote tf32 bits)
    uint32_t qf[2][8][4];
#pragma unroll
    for (int mt = 0; mt < 2; mt++) {
        const float* q0 = &g_q[((t0 + r0l + mt * 16)     * B_SZ + b) * EMB + h * HD];
        const float* q1 = &g_q[((t0 + r0l + mt * 16 + 8) * B_SZ + b) * EMB + h * HD];
#pragma unroll
        for (int ks = 0; ks < 8; ks++) {
            int kk = ks * 8;
            qf[mt][ks][0] = __float_as_uint(q0[kk + lc]);
            qf[mt][ks][1] = __float_as_uint(q1[kk + lc]);
            qf[mt][ks][2] = __float_as_uint(q0[kk + lc + 4]);
            qf[mt][ks][3] = __float_as_uint(q1[kk + lc + 4]);
        }
    }

    // bias slice (fold -M*log2e), mask row
    for (int i = tid; i < 2175; i += 128)
        sm[SMB + i] = g_bias[h * 4096 + i + 1921 - t0] - MAXS_L2E;
    ((float4*)smask)[tid] = ((const float4*)(maskg + b * T_LEN))[tid];

    issue_kv(0, 0); cp_commit();
    issue_kv(1, 1); cp_commit();

    float o[2][8][4];
#pragma unroll
    for (int mt = 0; mt < 2; mt++)
#pragma unroll
        for (int nt = 0; nt < 8; nt++)
#pragma unroll
            for (int i = 0; i < 4; i++) o[mt][nt][i] = 0.f;
    float ls[2][2] = {{0.f, 0.f}, {0.f, 0.f}};

    for (int kt = 0; kt < 64; kt++) {
        cp_wait<1>();
        __syncthreads();
        if (kt + 2 < 64) issue_kv(kt + 2, (kt + 2) % 3);
        cp_commit();

        int slot = kt % 3;
        const float* Ks = sm + SMK + slot * KSTG;
        const float* Vs = sm + SMV + slot * VSTG;
        int s0 = kt * 32;

        // S = Q K^T  (m32 x n32 x k64); K-frags reused across both m-tiles
        float s4[2][4][4];
#pragma unroll
        for (int mt = 0; mt < 2; mt++)
#pragma unroll
            for (int nt = 0; nt < 4; nt++)
#pragma unroll
                for (int i = 0; i < 4; i++) s4[mt][nt][i] = 0.f;
#pragma unroll
        for (int ks = 0; ks < 8; ks++) {
            int kk = ks * 8;
            uint32_t bf[4][2];
#pragma unroll
            for (int nt = 0; nt < 4; nt++) {
                int nb = nt * 8 + lr;
                bf[nt][0] = __float_as_uint(Ks[nb * KST + kk + lc]);
                bf[nt][1] = __float_as_uint(Ks[nb * KST + kk + lc + 4]);
            }
#pragma unroll
            for (int mt = 0; mt < 2; mt++)
#pragma unroll
                for (int nt = 0; nt < 4; nt++)
                    mma_tf32(s4[mt][nt], qf[mt][ks], bf[nt]);
        }

        // p = 2^( s*log2e + (bias - M)*log2e + mask )
#pragma unroll
        for (int mt = 0; mt < 2; mt++) {
            int ra = r0l + mt * 16, rb = ra + 8;
#pragma unroll
            for (int nt = 0; nt < 4; nt++) {
                int c0 = nt * 8 + 2 * lc, c1 = c0 + 1;
                float mk0 = smask[s0 + c0] ? -1e30f : 0.f;
                float mk1 = smask[s0 + c1] ? -1e30f : 0.f;
                float pb00 = sm[SMB + s0 + c0 - ra + 127] + mk0;
                float pb01 = sm[SMB + s0 + c1 - ra + 127] + mk1;
                float pb10 = sm[SMB + s0 + c0 - rb + 127] + mk0;
                float pb11 = sm[SMB + s0 + c1 - rb + 127] + mk1;
                s4[mt][nt][0] = ex2(fmaf(s4[mt][nt][0], L2E, pb00));
                s4[mt][nt][1] = ex2(fmaf(s4[mt][nt][1], L2E, pb01));
                s4[mt][nt][2] = ex2(fmaf(s4[mt][nt][2], L2E, pb10));
                s4[mt][nt][3] = ex2(fmaf(s4[mt][nt][3], L2E, pb11));
                ls[mt][0] += s4[mt][nt][0] + s4[mt][nt][1];
                ls[mt][1] += s4[mt][nt][2] + s4[mt][nt][3];
            }
        }

        // stage P (tf32, warp-private 32 rows)
#pragma unroll
        for (int mt = 0; mt < 2; mt++) {
            int ra = r0l + mt * 16, rb = ra + 8;
#pragma unroll
            for (int nt = 0; nt < 4; nt++) {
                int c0 = nt * 8 + 2 * lc;
                *(float2*)&sm[SMP + ra * PST + c0] =
                    make_float2(tff(s4[mt][nt][0]), tff(s4[mt][nt][1]));
                *(float2*)&sm[SMP + rb * PST + c0] =
                    make_float2(tff(s4[mt][nt][2]), tff(s4[mt][nt][3]));
            }
        }
        __syncwarp();

        // O += P V  (m32 x n64 x k32); V-frags reused across both m-tiles
#pragma unroll
        for (int ks = 0; ks < 4; ks++) {
            int kk = ks * 8;
            uint32_t a[2][4], bf[8][2];
#pragma unroll
            for (int mt = 0; mt < 2; mt++) {
                int ra = r0l + mt * 16;
                a[mt][0] = __float_as_uint(sm[SMP + ra * PST + kk + lc]);
                a[mt][1] = __float_as_uint(sm[SMP + (ra + 8) * PST + kk + lc]);
                a[mt][2] = __float_as_uint(sm[SMP + ra * PST + kk + lc + 4]);
                a[mt][3] = __float_as_uint(sm[SMP + (ra + 8) * PST + kk + lc + 4]);
            }
#pragma unroll
            for (int nt = 0; nt < 8; nt++) {
                int nb = nt * 8 + lr;
                bf[nt][0] = __float_as_uint(Vs[(kk + lc)     * VST + nb]);
                bf[nt][1] = __float_as_uint(Vs[(kk + lc + 4) * VST + nb]);
            }
#pragma unroll
            for (int mt = 0; mt < 2; mt++)
#pragma unroll
                for (int nt = 0; nt < 8; nt++)
                    mma_tf32(o[mt][nt], a[mt], bf[nt]);
        }
    }

    // deferred row-sum reduce (quads share rows)
#pragma unroll
    for (int mt = 0; mt < 2; mt++) {
#pragma unroll
        for (int i = 0; i < 2; i++) {
            ls[mt][i] += __shfl_xor_sync(0xffffffffu, ls[mt][i], 1);
            ls[mt][i] += __shfl_xor_sync(0xffffffffu, ls[mt][i], 2);
        }
    }

#pragma unroll
    for (int mt = 0; mt < 2; mt++) {
        float inv0 = 1.0f / ls[mt][0], inv1 = 1.0f / ls[mt][1];
        int tra = t0 + r0l + mt * 16;
#pragma unroll
        for (int nt = 0; nt < 8; nt++) {
            int d = h * HD + nt * 8 + 2 * lc;
            *(float2*)&g_att[(tra * B_SZ + b) * EMB + d] =
                make_float2(o[mt][nt][0] * inv0, o[mt][nt][1] * inv0);
            *(float2*)&g_att[((tra + 8) * B_SZ + b) * EMB + d] =
                make_float2(o[mt][nt][2] * inv1, o[mt][nt][3] * inv1);
        }
    }
}

// ---------------- launch ---------------------------------------------------
extern "C" void kernel_launch(void* const* d_in, const int* in_sizes, int n_in,
                              void* d_out, int out_size) {
    const float* query = (const float*)d_in[0];
    const float* key   = (const float*)d_in[1];
    const float* value = (const float*)d_in[2];
    const unsigned char* mask = (const unsigned char*)d_in[3];
    const float* Wq = (const float*)d_in[4];
    const float* bq = (const float*)d_in[5];
    const float* Wk = (const float*)d_in[6];
    const float* bk = (const float*)d_in[7];
    const float* Wv = (const float*)d_in[8];
    const float* bv = (const float*)d_in[9];
    const float* Wo = (const float*)d_in[10];
    const float* bo = (const float*)d_in[11];
    const float* rel_bias = (const float*)d_in[12];
    float* out = (float*)d_out;

    float *pq, *pk, *pv, *patt;
    cudaGetSymbolAddress((void**)&pq,   g_q);
    cudaGetSymbolAddress((void**)&pk,   g_k);
    cudaGetSymbolAddress((void**)&pv,   g_v);
    cudaGetSymbolAddress((void**)&patt, g_att);

    const int ATTN_SMEM = SMTOT * 4;   // 82944
    cudaFuncSetAttribute(attn_tf32_v5,
                         cudaFuncAttributeMaxDynamicSharedMemorySize, ATTN_SMEM);

    bias_lut_kernel<<<(NH * 4096 + 255) / 256, 256>>>(rel_bias);

    dim3 gg(EMB / 64, MROWS / 128);   // (12, 32) = 384 CTAs
    sgemm_tf32_kernel<true><<<gg, 256>>>(query, Wq, bq, pq, 0.125f);
    sgemm_tf32_kernel<true><<<gg, 256>>>(key,   Wk, bk, pk, 1.0f);
    sgemm_tf32_kernel<true><<<gg, 256>>>(value, Wv, bv, pv, 1.0f);

    dim3 ga(T_LEN / 128, B_SZ * NH);  // (16, 24)
    attn_tf32_v5<<<ga, 128, ATTN_SMEM>>>(mask);

    sgemm_tf32_kernel<false><<<gg, 256>>>(patt, Wo, bo, out, 1.0f);
}

// round 17
// speedup vs baseline: 1.1112x; 1.0483x over previous
#include <cuda_runtime.h>
#include <cuda_fp16.h>
#include <math.h>
#include <stdint.h>

#define T_LEN 2048
#define B_SZ  2
#define EMB   768
#define NH    12
#define HD    64
#define MROWS 4096
#define L2E   1.4426950408889634f
#define MAXS_L2E (24.0f * L2E)

// ---------------- scratch (device globals) ---------------------------------
__device__ __half g_qh[MROWS * EMB];
__device__ __half g_kh[MROWS * EMB];
__device__ float  g_v[MROWS * EMB];
__device__ float  g_att[MROWS * EMB];
__device__ float  g_bias[NH * 4096];  // [h][rel+2048], pre-scaled by log2(e)

// ---------------- helpers ---------------------------------------------------
__device__ __forceinline__ uint32_t smu32(const void* p) {
    uint32_t a;
    asm("{.reg .u64 t; cvta.to.shared.u64 t, %1; cvt.u32.u64 %0, t;}"
        : "=r"(a) : "l"(p));
    return a;
}
__device__ __forceinline__ void cp16(uint32_t d, const void* s) {
    asm volatile("cp.async.cg.shared.global [%0], [%1], 16;" :: "r"(d), "l"(s));
}
__device__ __forceinline__ void cp_commit() { asm volatile("cp.async.commit_group;"); }
template <int N> __device__ __forceinline__ void cp_wait() {
    asm volatile("cp.async.wait_group %0;" :: "n"(N));
}
__device__ __forceinline__ uint32_t tfu(float x) {
    uint32_t r;
    asm("cvt.rna.tf32.f32 %0, %1;" : "=r"(r) : "f"(x));
    return r;
}
__device__ __forceinline__ float tff(float x) { return __uint_as_float(tfu(x)); }
__device__ __forceinline__ float ex2(float x) {
    float r;
    asm("ex2.approx.f32 %0, %1;" : "=f"(r) : "f"(x));
    return r;
}
__device__ __forceinline__ void mma_tf32(float c[4], const uint32_t a[4],
                                         const uint32_t b[2]) {
    asm volatile(
        "mma.sync.aligned.m16n8k8.row.col.f32.tf32.tf32.f32 "
        "{%0,%1,%2,%3},{%4,%5,%6,%7},{%8,%9},{%0,%1,%2,%3};"
        : "+f"(c[0]), "+f"(c[1]), "+f"(c[2]), "+f"(c[3])
        : "r"(a[0]), "r"(a[1]), "r"(a[2]), "r"(a[3]), "r"(b[0]), "r"(b[1]));
}
__device__ __forceinline__ void mma_f16(float c[4], const uint32_t a[4],
                                        const uint32_t b[2]) {
    asm volatile(
        "mma.sync.aligned.m16n8k16.row.col.f32.f16.f16.f32 "
        "{%0,%1,%2,%3},{%4,%5,%6,%7},{%8,%9},{%0,%1,%2,%3};"
        : "+f"(c[0]), "+f"(c[1]), "+f"(c[2]), "+f"(c[3])
        : "r"(a[0]), "r"(a[1]), "r"(a[2]), "r"(a[3]), "r"(b[0]), "r"(b[1]));
}

// ---------------- T5 relative bias LUT (pre-scaled by log2 e) --------------
__global__ void bias_lut_kernel(const float* __restrict__ rel_bias) {
    int idx = blockIdx.x * blockDim.x + threadIdx.x;
    if (idx >= NH * 4096) return;
    int h   = idx >> 12;
    int rel = (idx & 4095) - 2048;
    int bucket = (rel > 0) ? 16 : 0;
    int rp = rel < 0 ? -rel : rel;
    if (rp < 8) {
        bucket += rp;
    } else {
        float lf = logf((float)rp / 8.0f) / 2.7725887298583984f * 8.0f;
        int large = 8 + (int)lf;
        bucket += (large < 15) ? large : 15;
    }
    g_bias[idx] = rel_bias[bucket * NH + h] * L2E;
}

// ---- tf32 SGEMM (round-15 engine); MODE: 0=f32, 1=f16, 2=f32 tf32-rounded -
#define ASTR 36    // ≡4 mod 32
#define BSTR 72    // ≡8 mod 32
template <int MODE>
__global__ __launch_bounds__(256, 3)
void sgemm_tf32_kernel(const float* __restrict__ X, const float* __restrict__ W,
                       const float* __restrict__ bias, void* __restrict__ Yv,
                       float scale) {
    __shared__ float As[128 * ASTR];
    __shared__ float Bs[32 * BSTR];

    int tid = threadIdx.x, lane = tid & 31, w = tid >> 5;
    int wm = w & 3, wn = w >> 2, lr = lane >> 2, lc = lane & 3;
    int m0 = blockIdx.y << 7, n0 = blockIdx.x << 6;

    float acc[2][4][4];
#pragma unroll
    for (int mt = 0; mt < 2; mt++)
#pragma unroll
        for (int nt = 0; nt < 4; nt++)
#pragma unroll
            for (int i = 0; i < 4; i++) acc[mt][nt][i] = 0.f;

    for (int k0 = 0; k0 < EMB; k0 += 32) {
        __syncthreads();
#pragma unroll
        for (int i = 0; i < 4; i++) {
            int e = tid + i * 256;
            int row = e >> 3, kc = (e & 7) << 2;
            float4 v = *(const float4*)&X[(m0 + row) * EMB + k0 + kc];
            v.x = tff(v.x); v.y = tff(v.y); v.z = tff(v.z); v.w = tff(v.w);
            *(float4*)&As[row * ASTR + kc] = v;
        }
#pragma unroll
        for (int i = 0; i < 2; i++) {
            int e = tid + i * 256;
            int k = e >> 4, nc = (e & 15) << 2;
            float4 v = *(const float4*)&W[(k0 + k) * EMB + n0 + nc];
            v.x = tff(v.x); v.y = tff(v.y); v.z = tff(v.z); v.w = tff(v.w);
            *(float4*)&Bs[k * BSTR + nc] = v;
        }
        __syncthreads();

#pragma unroll
        for (int ks = 0; ks < 4; ks++) {
            int kk = ks * 8;
            uint32_t a[2][4], bf[4][2];
#pragma unroll
            for (int mt = 0; mt < 2; mt++) {
                int base = wm * 32 + mt * 16;
                a[mt][0] = __float_as_uint(As[(base + lr)     * ASTR + kk + lc]);
                a[mt][1] = __float_as_uint(As[(base + lr + 8) * ASTR + kk + lc]);
                a[mt][2] = __float_as_uint(As[(base + lr)     * ASTR + kk + lc + 4]);
                a[mt][3] = __float_as_uint(As[(base + lr + 8) * ASTR + kk + lc + 4]);
            }
#pragma unroll
            for (int nt = 0; nt < 4; nt++) {
                int nb = wn * 32 + nt * 8 + lr;
                bf[nt][0] = __float_as_uint(Bs[(kk + lc)     * BSTR + nb]);
                bf[nt][1] = __float_as_uint(Bs[(kk + lc + 4) * BSTR + nb]);
            }
#pragma unroll
            for (int mt = 0; mt < 2; mt++)
#pragma unroll
                for (int nt = 0; nt < 4; nt++)
                    mma_tf32(acc[mt][nt], a[mt], bf[nt]);
        }
    }

#pragma unroll
    for (int mt = 0; mt < 2; mt++) {
        int row = m0 + wm * 32 + mt * 16 + lr;
#pragma unroll
        for (int nt = 0; nt < 4; nt++) {
            int col = n0 + wn * 32 + nt * 8 + 2 * lc;
            float b0 = bias[col], b1 = bias[col + 1];
            float o00 = (acc[mt][nt][0] + b0) * scale;
            float o01 = (acc[mt][nt][1] + b1) * scale;
            float o10 = (acc[mt][nt][2] + b0) * scale;
            float o11 = (acc[mt][nt][3] + b1) * scale;
            if (MODE == 1) {
                __half* Y = (__half*)Yv;
                *(__half2*)&Y[row * EMB + col]       = __floats2half2_rn(o00, o01);
                *(__half2*)&Y[(row + 8) * EMB + col] = __floats2half2_rn(o10, o11);
            } else {
                if (MODE == 2) { o00 = tff(o00); o01 = tff(o01); o10 = tff(o10); o11 = tff(o11); }
                float* Y = (float*)Yv;
                *(float2*)&Y[row * EMB + col]       = make_float2(o00, o01);
                *(float2*)&Y[(row + 8) * EMB + col] = make_float2(o10, o11);
            }
        }
    }
}

// ---- flash attention v7: fp16 QK (m16n8k16) + tf32 PV (round-15 path) -----
#define KSTH 72              // K row stride, halfs (144 B rows)
#define VSTF 72              // V row stride, floats
#define PSTF 36
#define KSTG_B 4608          // 32*72*2
#define VSTG_B 9216          // 32*72*4
#define SMK_O 0
#define SMV_O 13824          // 3*KSTG_B
#define SMP_O 41472          // SMV_O + 3*VSTG_B
#define SMB_O 59904          // SMP_O + 128*36*4
#define SMM_O 68608          // SMB_O + 2175*4, padded
#define SMTOT_O 70656

#define SMP_F (SMP_O / 4)
#define SMB_F (SMB_O / 4)

__global__ __launch_bounds__(128, 2)
void attn_v7(const unsigned char* __restrict__ maskg) {
    extern __shared__ char smc[];
    float* smf = (float*)smc;
    int tid = threadIdx.x, lane = tid & 31, w = tid >> 5;   // w in [0,4)
    int lr = lane >> 2, lc = lane & 3;
    int bh = blockIdx.y;
    int b = bh / NH, h = bh % NH;
    int t0 = blockIdx.x * 128;
    uint32_t sbase = smu32(smc);
    unsigned char* smask = (unsigned char*)(smc + SMM_O);
    int r0l = w * 32 + lr;                 // warp rows [w*32, w*32+32)

    auto issue_kv = [&](int kt2, int slot) {
        int s0 = kt2 * 32;
        // K tile: 32 rows x 64 halfs (256 16B chunks)
#pragma unroll
        for (int i = 0; i < 2; i++) {
            int e = tid + i * 128;
            int row = e >> 3, c8 = e & 7;
            cp16(sbase + SMK_O + slot * KSTG_B + (row * KSTH + c8 * 8) * 2,
                 g_kh + ((s0 + row) * B_SZ + b) * EMB + h * HD + c8 * 8);
        }
        // V tile: 32 rows x 64 floats (512 16B chunks)
#pragma unroll
        for (int i = 0; i < 4; i++) {
            int e = tid + i * 128;
            int row = e >> 4, c4 = (e & 15) << 2;
            cp16(sbase + SMV_O + slot * VSTG_B + (row * VSTF + c4) * 4,
                 g_v + ((s0 + row) * B_SZ + b) * EMB + h * HD + c4);
        }
    };

    // Q fragments (fp16, loop-invariant, straight from gmem)
    uint32_t qf[2][4][4];
#pragma unroll
    for (int mt = 0; mt < 2; mt++) {
        const __half* q0 = g_qh + ((t0 + r0l + mt * 16)     * B_SZ + b) * EMB + h * HD;
        const __half* q1 = g_qh + ((t0 + r0l + mt * 16 + 8) * B_SZ + b) * EMB + h * HD;
#pragma unroll
        for (int ks = 0; ks < 4; ks++) {
            int col = ks * 16 + 2 * lc;
            qf[mt][ks][0] = *(const uint32_t*)(q0 + col);
            qf[mt][ks][1] = *(const uint32_t*)(q1 + col);
            qf[mt][ks][2] = *(const uint32_t*)(q0 + col + 8);
            qf[mt][ks][3] = *(const uint32_t*)(q1 + col + 8);
        }
    }

    // bias slice (fold -M*log2e), mask row
    for (int i = tid; i < 2175; i += 128)
        smf[SMB_F + i] = g_bias[h * 4096 + i + 1921 - t0] - MAXS_L2E;
    ((float4*)smask)[tid] = ((const float4*)(maskg + b * T_LEN))[tid];

    issue_kv(0, 0); cp_commit();
    issue_kv(1, 1); cp_commit();

    float o[2][8][4];
#pragma unroll
    for (int mt = 0; mt < 2; mt++)
#pragma unroll
        for (int nt = 0; nt < 8; nt++)
#pragma unroll
            for (int i = 0; i < 4; i++) o[mt][nt][i] = 0.f;
    float ls[2][2] = {{0.f, 0.f}, {0.f, 0.f}};

    for (int kt = 0; kt < 64; kt++) {
        cp_wait<1>();
        __syncthreads();
        if (kt + 2 < 64) issue_kv(kt + 2, (kt + 2) % 3);
        cp_commit();

        int slot = kt % 3;
        const __half* Ks = (const __half*)(smc + SMK_O + slot * KSTG_B);
        const float*  Vs = (const float*)(smc + SMV_O + slot * VSTG_B);
        int s0 = kt * 32;

        // S = Q K^T  (m32 x n32 x k64), fp16 m16n8k16
        float s4[2][4][4];
#pragma unroll
        for (int mt = 0; mt < 2; mt++)
#pragma unroll
            for (int nt = 0; nt < 4; nt++)
#pragma unroll
                for (int i = 0; i < 4; i++) s4[mt][nt][i] = 0.f;
#pragma unroll
        for (int ks = 0; ks < 4; ks++) {
            uint32_t bf[4][2];
#pragma unroll
            for (int nt = 0; nt < 4; nt++) {
                const __half* kp = Ks + (nt * 8 + lr) * KSTH + ks * 16 + 2 * lc;
                bf[nt][0] = *(const uint32_t*)kp;
                bf[nt][1] = *(const uint32_t*)(kp + 8);
            }
#pragma unroll
            for (int mt = 0; mt < 2; mt++)
#pragma unroll
                for (int nt = 0; nt < 4; nt++)
                    mma_f16(s4[mt][nt], qf[mt][ks], bf[nt]);
        }

        // p = 2^( s*log2e + (bias - M)*log2e + mask )
#pragma unroll
        for (int mt = 0; mt < 2; mt++) {
            int ra = r0l + mt * 16, rb = ra + 8;
#pragma unroll
            for (int nt = 0; nt < 4; nt++) {
                int c0 = nt * 8 + 2 * lc, c1 = c0 + 1;
                float mk0 = smask[s0 + c0] ? -1e30f : 0.f;
                float mk1 = smask[s0 + c1] ? -1e30f : 0.f;
                float pb00 = smf[SMB_F + s0 + c0 - ra + 127] + mk0;
                float pb01 = smf[SMB_F + s0 + c1 - ra + 127] + mk1;
                float pb10 = smf[SMB_F + s0 + c0 - rb + 127] + mk0;
                float pb11 = smf[SMB_F + s0 + c1 - rb + 127] + mk1;
                s4[mt][nt][0] = ex2(fmaf(s4[mt][nt][0], L2E, pb00));
                s4[mt][nt][1] = ex2(fmaf(s4[mt][nt][1], L2E, pb01));
                s4[mt][nt][2] = ex2(fmaf(s4[mt][nt][2], L2E, pb10));
                s4[mt][nt][3] = ex2(fmaf(s4[mt][nt][3], L2E, pb11));
                ls[mt][0] += s4[mt][nt][0] + s4[mt][nt][1];
                ls[mt][1] += s4[mt][nt][2] + s4[mt][nt][3];
            }
        }

        // stage P (tf32, warp-private 32 rows) — round-15 path
#pragma unroll
        for (int mt = 0; mt < 2; mt++) {
            int ra = r0l + mt * 16, rb = ra + 8;
#pragma unroll
            for (int nt = 0; nt < 4; nt++) {
                int c0 = nt * 8 + 2 * lc;
                *(float2*)&smf[SMP_F + ra * PSTF + c0] =
                    make_float2(tff(s4[mt][nt][0]), tff(s4[mt][nt][1]));
                *(float2*)&smf[SMP_F + rb * PSTF + c0] =
                    make_float2(tff(s4[mt][nt][2]), tff(s4[mt][nt][3]));
            }
        }
        __syncwarp();

        // O += P V  (m32 x n64 x k32), tf32 — round-15 path
#pragma unroll
        for (int ks = 0; ks < 4; ks++) {
            int kk = ks * 8;
            uint32_t a[2][4], bf[8][2];
#pragma unroll
            for (int mt = 0; mt < 2; mt++) {
                int ra = r0l + mt * 16;
                a[mt][0] = __float_as_uint(smf[SMP_F + ra * PSTF + kk + lc]);
                a[mt][1] = __float_as_uint(smf[SMP_F + (ra + 8) * PSTF + kk + lc]);
                a[mt][2] = __float_as_uint(smf[SMP_F + ra * PSTF + kk + lc + 4]);
                a[mt][3] = __float_as_uint(smf[SMP_F + (ra + 8) * PSTF + kk + lc + 4]);
            }
#pragma unroll
            for (int nt = 0; nt < 8; nt++) {
                int nb = nt * 8 + lr;
                bf[nt][0] = __float_as_uint(Vs[(kk + lc)     * VSTF + nb]);
                bf[nt][1] = __float_as_uint(Vs[(kk + lc + 4) * VSTF + nb]);
            }
#pragma unroll
            for (int mt = 0; mt < 2; mt++)
#pragma unroll
                for (int nt = 0; nt < 8; nt++)
                    mma_tf32(o[mt][nt], a[mt], bf[nt]);
        }
    }

    // deferred row-sum reduce (quads share rows)
#pragma unroll
    for (int mt = 0; mt < 2; mt++)
#pragma unroll
        for (int i = 0; i < 2; i++) {
            ls[mt][i] += __shfl_xor_sync(0xffffffffu, ls[mt][i], 1);
            ls[mt][i] += __shfl_xor_sync(0xffffffffu, ls[mt][i], 2);
        }

#pragma unroll
    for (int mt = 0; mt < 2; mt++) {
        float inv0 = 1.0f / ls[mt][0], inv1 = 1.0f / ls[mt][1];
        int tra = t0 + r0l + mt * 16;
#pragma unroll
        for (int nt = 0; nt < 8; nt++) {
            int d = h * HD + nt * 8 + 2 * lc;
            *(float2*)&g_att[(tra * B_SZ + b) * EMB + d] =
                make_float2(o[mt][nt][0] * inv0, o[mt][nt][1] * inv0);
            *(float2*)&g_att[((tra + 8) * B_SZ + b) * EMB + d] =
                make_float2(o[mt][nt][2] * inv1, o[mt][nt][3] * inv1);
        }
    }
}

// ---------------- launch ---------------------------------------------------
extern "C" void kernel_launch(void* const* d_in, const int* in_sizes, int n_in,
                              void* d_out, int out_size) {
    const float* query = (const float*)d_in[0];
    const float* key   = (const float*)d_in[1];
    const float* value = (const float*)d_in[2];
    const unsigned char* mask = (const unsigned char*)d_in[3];
    const float* Wq = (const float*)d_in[4];
    const float* bq = (const float*)d_in[5];
    const float* Wk = (const float*)d_in[6];
    const float* bk = (const float*)d_in[7];
    const float* Wv = (const float*)d_in[8];
    const float* bv = (const float*)d_in[9];
    const float* Wo = (const float*)d_in[10];
    const float* bo = (const float*)d_in[11];
    const float* rel_bias = (const float*)d_in[12];
    float* out = (float*)d_out;

    void *pq, *pk, *pv, *patt;
    cudaGetSymbolAddress(&pq,   g_qh);
    cudaGetSymbolAddress(&pk,   g_kh);
    cudaGetSymbolAddress(&pv,   g_v);
    cudaGetSymbolAddress(&patt, g_att);

    cudaFuncSetAttribute(attn_v7,
                         cudaFuncAttributeMaxDynamicSharedMemorySize, SMTOT_O);

    bias_lut_kernel<<<(NH * 4096 + 255) / 256, 256>>>(rel_bias);

    dim3 gg(EMB / 64, MROWS / 128);   // (12, 32) = 384 CTAs
    sgemm_tf32_kernel<1><<<gg, 256>>>(query, Wq, bq, pq, 0.125f);
    sgemm_tf32_kernel<1><<<gg, 256>>>(key,   Wk, bk, pk, 1.0f);
    sgemm_tf32_kernel<2><<<gg, 256>>>(value, Wv, bv, pv, 1.0f);

    dim3 ga(T_LEN / 128, B_SZ * NH);  // (16, 24)
    attn_v7<<<ga, 128, SMTOT_O>>>(mask);

    sgemm_tf32_kernel<0><<<gg, 256>>>((const float*)patt, Wo, bo, out, 1.0f);
}